// round 8
// baseline (speedup 1.0000x reference)
#include <cuda_runtime.h>
#include <cuda_bf16.h>
#include <math.h>

#define BATCH 2
#define CIN   64
#define COUT  128
#define HH    128
#define WW    128
#define HWSZ  (HH*WW)          // 16384
#define K1    576              // 9*64
#define K2C   1152             // 9*128
#define K2    1216             // + 64 identity rows

// ---------------- scratch (static device globals) ----------------------------
__device__ float g_off[BATCH * 18 * HWSZ];
__device__ float g_offp[8 * BATCH * 18 * HWSZ];             // per-chunk partials
__device__ float g_h1 [BATCH * COUT * HWSZ];
__device__ __nv_bfloat16 g_w1h[COUT * K1], g_w1l[COUT * K1];
__device__ __nv_bfloat16 g_w2h[COUT * K2], g_w2l[COUT * K2];
__device__ float g_b1[COUT], g_b2[COUT];
__device__ float g_s1[COUT], g_s2[COUT], g_s3[COUT];

// ---------------- PTX helpers (sm_80-era only; compute_103-safe) -------------
__device__ __forceinline__ unsigned smem_u32(const void* p) {
    unsigned a;
    asm("{ .reg .u64 t; cvta.to.shared.u64 t, %1; cvt.u32.u64 %0, t; }"
        : "=r"(a) : "l"(p));
    return a;
}
__device__ __forceinline__ void cp16(unsigned dst, const void* src) {
    asm volatile("cp.async.cg.shared.global [%0], [%1], 16;"
                 :: "r"(dst), "l"(src) : "memory");
}
__device__ __forceinline__ void cp_commit() {
    asm volatile("cp.async.commit_group;" ::: "memory");
}
__device__ __forceinline__ void cp_wait0() {
    asm volatile("cp.async.wait_group 0;" ::: "memory");
}
__device__ __forceinline__ void ldm_x4(unsigned a, unsigned r[4]) {
    asm volatile("ldmatrix.sync.aligned.m8n8.x4.shared.b16 {%0,%1,%2,%3}, [%4];"
                 : "=r"(r[0]), "=r"(r[1]), "=r"(r[2]), "=r"(r[3]) : "r"(a));
}
__device__ __forceinline__ void mma16816(float d[4], const unsigned a[4],
                                         unsigned b0, unsigned b1) {
    asm volatile(
        "mma.sync.aligned.m16n8k16.row.col.f32.bf16.bf16.f32 "
        "{%0,%1,%2,%3}, {%4,%5,%6,%7}, {%8,%9}, {%0,%1,%2,%3};"
        : "+f"(d[0]), "+f"(d[1]), "+f"(d[2]), "+f"(d[3])
        : "r"(a[0]), "r"(a[1]), "r"(a[2]), "r"(a[3]), "r"(b0), "r"(b1));
}
__device__ __forceinline__ unsigned pack_bf2(float a, float b) {
    return (unsigned)__bfloat16_as_ushort(__float2bfloat16(a)) |
           ((unsigned)__bfloat16_as_ushort(__float2bfloat16(b)) << 16);
}

// ---------------- weight prep ------------------------------------------------
__global__ void prep_scales(const float* __restrict__ bn1_g, const float* __restrict__ bn1_b,
                            const float* __restrict__ bn1_m, const float* __restrict__ bn1_v,
                            const float* __restrict__ bn2_g, const float* __restrict__ bn2_b,
                            const float* __restrict__ bn2_m, const float* __restrict__ bn2_v,
                            const float* __restrict__ id_b,
                            const float* __restrict__ bn3_g, const float* __restrict__ bn3_b,
                            const float* __restrict__ bn3_m, const float* __restrict__ bn3_v)
{
    int o = threadIdx.x;
    if (o >= COUT) return;
    const float eps = 1e-5f;
    float s1 = bn1_g[o] * rsqrtf(bn1_v[o] + eps);
    float s2 = bn2_g[o] * rsqrtf(bn2_v[o] + eps);
    float s3 = bn3_g[o] * rsqrtf(bn3_v[o] + eps);
    g_s1[o] = s1; g_s2[o] = s2; g_s3[o] = s3;
    g_b1[o] = bn1_b[o] - bn1_m[o] * s1;
    g_b2[o] = (bn2_b[o] - bn2_m[o] * s2) + id_b[o] * s3 + (bn3_b[o] - bn3_m[o] * s3);
}

__device__ __forceinline__ void split_store(__nv_bfloat16* hd, __nv_bfloat16* ld,
                                            long i, float v) {
    __nv_bfloat16 h = __float2bfloat16(v);
    hd[i] = h;
    ld[i] = __float2bfloat16(v - __bfloat162float(h));
}

__global__ void prep_weights(const float* __restrict__ dc1_w,
                             const float* __restrict__ dc2_w,
                             const float* __restrict__ id_w)
{
    int idx = blockIdx.x * blockDim.x + threadIdx.x;
    const int n1 = COUT * K1, n2 = COUT * K2C, n3 = COUT * CIN;
    if (idx < n1) {
        int o = idx / K1, kk = idx % K1;
        int c = kk / 9, n = kk % 9;
        float v = dc1_w[idx] * g_s1[o];
        split_store(g_w1h, g_w1l, (long)o * K1 + n * CIN + c, v);
    } else if (idx < n1 + n2) {
        int r = idx - n1;
        int o = r / K2C, kk = r % K2C;
        int c = kk / 9, n = kk % 9;
        float v = dc2_w[r] * g_s2[o];
        split_store(g_w2h, g_w2l, (long)o * K2 + n * COUT + c, v);
    } else if (idx < n1 + n2 + n3) {
        int r = idx - n1 - n2;
        int o = r / CIN, c = r % CIN;
        float v = id_w[r] * g_s3[o];
        split_store(g_w2h, g_w2l, (long)o * K2 + K2C + c, v);
    }
}

// ---------------- offset conv: smem-tiled partial conv -----------------------
__global__ __launch_bounds__(128)
void offset_partial_kernel(const float* __restrict__ xext, int use_h1,
                           const float* __restrict__ ow, int C)
{
    __shared__ float xs[16][324];
    __shared__ float ws[16 * 9 * 18];
    const float* x = use_h1 ? g_h1 : xext;
    const int CH = C / 16;
    const int z = blockIdx.z;
    const int b = z / CH, ch = z % CH, c0 = ch * 16;
    const int tx0 = blockIdx.x * 16, ty0 = blockIdx.y * 16;
    const int t = threadIdx.x;
    const int py = t >> 4, px = t & 15;

    for (int i = t; i < 16 * 162; i += 128) {
        int c = i / 162, r = i % 162, tap = r / 18, o = r % 18;
        ws[i] = ow[o * C * 9 + (c0 + c) * 9 + tap];
    }
    for (int i = t; i < 16 * 324; i += 128) {
        int c = i / 324, rr = (i % 324) / 18, cc = i % 18;
        int gy = ty0 - 1 + rr, gx = tx0 - 1 + cc;
        float v = 0.f;
        if ((unsigned)gy < (unsigned)HH && (unsigned)gx < (unsigned)WW)
            v = x[((long)b * C + c0 + c) * HWSZ + gy * WW + gx];
        xs[c][rr * 18 + cc] = v;
    }
    __syncthreads();

    float acc[2][18];
#pragma unroll
    for (int q = 0; q < 2; ++q)
#pragma unroll
        for (int o = 0; o < 18; ++o) acc[q][o] = 0.f;

    for (int c = 0; c < 16; ++c) {
#pragma unroll
        for (int tap = 0; tap < 9; ++tap) {
            int ky = tap / 3, kx = tap % 3;
            float xv0 = xs[c][(py + ky) * 18 + px + kx];
            float xv1 = xs[c][(py + 8 + ky) * 18 + px + kx];
            const float* wrow = &ws[(c * 9 + tap) * 18];
#pragma unroll
            for (int o = 0; o < 18; ++o) {
                float w = wrow[o];
                acc[0][o] += w * xv0;
                acc[1][o] += w * xv1;
            }
        }
    }

    float* pp = g_offp + (long)ch * (BATCH * 18 * HWSZ);
#pragma unroll
    for (int q = 0; q < 2; ++q) {
        int row = ty0 + py + q * 8;
#pragma unroll
        for (int o = 0; o < 18; ++o)
            pp[((long)b * 18 + o) * HWSZ + row * WW + tx0 + px] = acc[q][o];
    }
}

__global__ void offset_reduce_kernel(const float* __restrict__ ob, int CH)
{
    int idx = blockIdx.x * blockDim.x + threadIdx.x;
    const int total = BATCH * 18 * HWSZ;
    if (idx >= total) return;
    int o = (idx / HWSZ) % 18;
    float s = ob[o];
    for (int c = 0; c < CH; ++c)
        s += g_offp[(long)c * total + idx];
    g_off[idx] = s;
}

// ---------------- fused sample + HMMA bf16x3 GEMM + bias + relu --------------
// Per CTA: 64 pixels (N) x 128 Cout (M); K-chunks of 16. B tile produced in-kernel.
// NOTE: all __device__ globals are resolved INSIDE the kernel (template SEL),
// never passed as host-side arguments.
#define ROWB2 48
#define A_MAT (128 * ROWB2)          // 6144
#define A_BUF (2 * A_MAT)            // 12288 (hi+lo)
#define B_MAT (64 * ROWB2)           // 3072
#define B_BUF (2 * B_MAT)            // 6144
#define SM_W4 0
#define SM_J4 9216
#define SM_A  18432
#define SM_B  (SM_A + 2 * A_BUF)     // 43008
#define FGEMM_SMEM (SM_B + 2 * B_BUF) // 55296

template<int C, int KTOT, int NCH, int CSH, int IDST, int SEL>
__global__ __launch_bounds__(256, 2)
void fused_gemm_kernel(const float* __restrict__ xptr, float* __restrict__ dout)
{
    extern __shared__ char sm[];
    float4* sw4 = (float4*)(sm + SM_W4);
    int4*   sj4 = (int4*)(sm + SM_J4);

    // device-side pointer resolution (the R7 bug fix)
    const __nv_bfloat16* Ah = SEL ? g_w2h : g_w1h;
    const __nv_bfloat16* Al = SEL ? g_w2l : g_w1l;
    const float* bias       = SEL ? g_b2  : g_b1;
    float* Cp               = SEL ? dout  : g_h1;
    const float* src        = SEL ? g_h1  : xptr;

    const int tid = threadIdx.x;
    const int warp = tid >> 5, lane = tid & 31;
    const int mbase = (warp >> 1) * 32;
    const int nbase = (warp & 1) * 32;
    const int b = blockIdx.y, j0 = blockIdx.x * 64;
    const unsigned sb = smem_u32(sm);

    // ---- precompute bilinear weights/indices for 64 px x 9 taps ----
    for (int i = tid; i < 576; i += 256) {
        int n = i >> 6, pxl = i & 63;
        int pix = j0 + pxl;
        int hh = pix >> 7, ww = pix & 127;
        float offy = g_off[(b * 18 + n)     * HWSZ + pix];
        float offx = g_off[(b * 18 + 9 + n) * HWSZ + pix];
        float py = offy + (float)(n / 3 - 1) + (float)(hh + 1);
        float px = offx + (float)(n % 3 - 1) + (float)(ww + 1);
        const float hiB = 129.f;
        py = fminf(fmaxf(py, 0.f), hiB);
        px = fminf(fmaxf(px, 0.f), hiB);
        float fy = floorf(py), fx = floorf(px);
        float qy1 = fminf(fy + 1.f, hiB), qx1 = fminf(fx + 1.f, hiB);
        float dy0 = 1.f + (fy - py), dy1 = 1.f - (qy1 - py);
        float dx0 = 1.f + (fx - px), dx1 = 1.f - (qx1 - px);
        int iy0 = (int)fy - 1, ix0 = (int)fx - 1;
        int iy1 = (int)qy1 - 1, ix1 = (int)qx1 - 1;
        bool vy0 = (unsigned)iy0 < (unsigned)HH, vy1 = (unsigned)iy1 < (unsigned)HH;
        bool vx0 = (unsigned)ix0 < (unsigned)WW, vx1 = (unsigned)ix1 < (unsigned)WW;
        float w00 = (vy0 && vx0) ? dy0 * dx0 : 0.f;
        float w01 = (vy0 && vx1) ? dy0 * dx1 : 0.f;
        float w10 = (vy1 && vx0) ? dy1 * dx0 : 0.f;
        float w11 = (vy1 && vx1) ? dy1 * dx1 : 0.f;
        int cy0 = min(max(iy0, 0), HH - 1), cy1 = min(max(iy1, 0), HH - 1);
        int cx0 = min(max(ix0, 0), WW - 1), cx1 = min(max(ix1, 0), WW - 1);
        sw4[i] = make_float4(w00, w01, w10, w11);
        sj4[i] = make_int4(cy0 * WW + cx0, cy0 * WW + cx1,
                           cy1 * WW + cx0, cy1 * WW + cx1);
    }

    float d[2][4][4];
#pragma unroll
    for (int mt = 0; mt < 2; ++mt)
#pragma unroll
        for (int nt = 0; nt < 4; ++nt)
#pragma unroll
            for (int q = 0; q < 4; ++q) d[mt][nt][q] = 0.f;

    const int e = tid & 3, pxl = tid >> 2;
    const int pix = j0 + pxl;
    const float* srcb = src + (long)b * C * HWSZ;
    const float* xb   = xptr + (long)b * CIN * HWSZ;

    float v[4];
    auto gather = [&](int ch) {
        if (ch < IDST) {
            int n = ch >> CSH, c0 = (ch & ((1 << CSH) - 1)) * 16;
            int pi = (n << 6) | pxl;
            float4 wv = sw4[pi];
            int4 jv = sj4[pi];
#pragma unroll
            for (int u = 0; u < 4; ++u) {
                const float* pc = srcb + (long)(c0 + e * 4 + u) * HWSZ;
                v[u] = wv.x * pc[jv.x] + wv.y * pc[jv.y]
                     + wv.z * pc[jv.z] + wv.w * pc[jv.w];
            }
        } else {
            int c0 = (ch - IDST) * 16;
#pragma unroll
            for (int u = 0; u < 4; ++u)
                v[u] = xb[(long)(c0 + e * 4 + u) * HWSZ + pix];
        }
    };
    auto storeB = [&](unsigned p) {
        unsigned h0 = pack_bf2(v[0], v[1]);
        unsigned h1 = pack_bf2(v[2], v[3]);
        unsigned l0 = pack_bf2(v[0] - __bfloat162float(__float2bfloat16(v[0])),
                               v[1] - __bfloat162float(__float2bfloat16(v[1])));
        unsigned l1 = pack_bf2(v[2] - __bfloat162float(__float2bfloat16(v[2])),
                               v[3] - __bfloat162float(__float2bfloat16(v[3])));
        char* base = sm + SM_B + p * B_BUF + pxl * ROWB2 + e * 8;
        *(uint2*)(base)         = make_uint2(h0, h1);
        *(uint2*)(base + B_MAT) = make_uint2(l0, l1);
    };
    auto loadA = [&](int ch, unsigned p) {
        int k0 = ch * 16;
        int r = tid >> 1, seg = tid & 1;
        unsigned dst = sb + SM_A + p * A_BUF + r * ROWB2 + seg * 16;
        cp16(dst,         Ah + (long)r * KTOT + k0 + seg * 8);
        cp16(dst + A_MAT, Al + (long)r * KTOT + k0 + seg * 8);
        cp_commit();
    };

    const unsigned a_off = (unsigned)(mbase + (lane & 15)) * ROWB2 +
                           (unsigned)((lane >> 4) & 1) * 16u;
    const unsigned b_off = (unsigned)(nbase + (lane & 7) + (((lane >> 4) & 1) << 3)) * ROWB2 +
                           (unsigned)((lane >> 3) & 1) * 16u;

    __syncthreads();          // precomp visible
    gather(0);
    storeB(0);
    loadA(0, 0);

    unsigned p = 0;
    for (int ch = 0; ch < NCH; ++ch) {
        cp_wait0();
        __syncthreads();
        if (ch + 1 < NCH) {
            gather(ch + 1);
            loadA(ch + 1, p ^ 1);
        }
        {
            unsigned abase = sb + SM_A + p * A_BUF;
            unsigned bbase = sb + SM_B + p * B_BUF;
            unsigned ah[2][4], al[2][4], bh[2][4], bl[2][4];
#pragma unroll
            for (int mt = 0; mt < 2; ++mt) {
                unsigned addr = abase + a_off + mt * 16u * ROWB2;
                ldm_x4(addr, ah[mt]);
                ldm_x4(addr + A_MAT, al[mt]);
            }
#pragma unroll
            for (int np = 0; np < 2; ++np) {
                unsigned addr = bbase + b_off + np * 16u * ROWB2;
                ldm_x4(addr, bh[np]);
                ldm_x4(addr + B_MAT, bl[np]);
            }
#pragma unroll
            for (int mt = 0; mt < 2; ++mt) {
#pragma unroll
                for (int nt = 0; nt < 4; ++nt) {
                    int np = nt >> 1, rp = (nt & 1) * 2;
                    mma16816(d[mt][nt], ah[mt], bh[np][rp], bh[np][rp + 1]);
                    mma16816(d[mt][nt], ah[mt], bl[np][rp], bl[np][rp + 1]);
                    mma16816(d[mt][nt], al[mt], bh[np][rp], bh[np][rp + 1]);
                }
            }
        }
        if (ch + 1 < NCH) storeB(p ^ 1);
        p ^= 1;
    }

    // epilogue: bias + relu
    const int qr = lane >> 2;
    const int qc = (lane & 3) * 2;
#pragma unroll
    for (int mt = 0; mt < 2; ++mt) {
        int o0 = mbase + mt * 16 + qr;
        int o1 = o0 + 8;
        float bs0 = bias[o0], bs1 = bias[o1];
        float* row0 = Cp + ((long)b * COUT + o0) * HWSZ + j0 + nbase + qc;
        float* row1 = Cp + ((long)b * COUT + o1) * HWSZ + j0 + nbase + qc;
#pragma unroll
        for (int nt = 0; nt < 4; ++nt) {
            float* acc = d[mt][nt];
            *(float2*)(row0 + nt * 8) =
                make_float2(fmaxf(acc[0] + bs0, 0.f), fmaxf(acc[1] + bs0, 0.f));
            *(float2*)(row1 + nt * 8) =
                make_float2(fmaxf(acc[2] + bs1, 0.f), fmaxf(acc[3] + bs1, 0.f));
        }
    }
}

// ---------------- launch -----------------------------------------------------
extern "C" void kernel_launch(void* const* d_in, const int* in_sizes, int n_in,
                              void* d_out, int out_size)
{
    const float* x        = (const float*)d_in[0];
    const float* dc1_offw = (const float*)d_in[1];
    const float* dc1_offb = (const float*)d_in[2];
    const float* dc1_w    = (const float*)d_in[3];
    const float* bn1_g    = (const float*)d_in[4];
    const float* bn1_b    = (const float*)d_in[5];
    const float* bn1_m    = (const float*)d_in[6];
    const float* bn1_v    = (const float*)d_in[7];
    const float* dc2_offw = (const float*)d_in[8];
    const float* dc2_offb = (const float*)d_in[9];
    const float* dc2_w    = (const float*)d_in[10];
    const float* bn2_g    = (const float*)d_in[11];
    const float* bn2_b    = (const float*)d_in[12];
    const float* bn2_m    = (const float*)d_in[13];
    const float* bn2_v    = (const float*)d_in[14];
    const float* id_w     = (const float*)d_in[15];
    const float* id_b     = (const float*)d_in[16];
    const float* bn3_g    = (const float*)d_in[17];
    const float* bn3_b    = (const float*)d_in[18];
    const float* bn3_m    = (const float*)d_in[19];
    const float* bn3_v    = (const float*)d_in[20];
    float* out = (float*)d_out;

    // sel1: C=64, K=576, 36 chunks, 4 chunks/tap (shift 2), no identity
    auto k1 = fused_gemm_kernel<CIN, K1, 36, 2, 36, 0>;
    // sel2: C=128, K=1216, 76 chunks, 8 chunks/tap (shift 3), identity from 72
    auto k2 = fused_gemm_kernel<COUT, K2, 76, 3, 72, 1>;
    cudaFuncSetAttribute(k1, cudaFuncAttributeMaxDynamicSharedMemorySize, FGEMM_SMEM);
    cudaFuncSetAttribute(k2, cudaFuncAttributeMaxDynamicSharedMemorySize, FGEMM_SMEM);

    prep_scales<<<1, 128>>>(bn1_g, bn1_b, bn1_m, bn1_v,
                            bn2_g, bn2_b, bn2_m, bn2_v,
                            id_b, bn3_g, bn3_b, bn3_m, bn3_v);
    {
        int total = COUT * K1 + COUT * K2C + COUT * CIN;
        prep_weights<<<(total + 255) / 256, 256>>>(dc1_w, dc2_w, id_w);
    }

    const int RED_N = BATCH * 18 * HWSZ;

    // layer 1
    offset_partial_kernel<<<dim3(WW / 16, HH / 16, BATCH * (CIN / 16)), 128>>>(
        x, 0, dc1_offw, CIN);
    offset_reduce_kernel<<<(RED_N + 255) / 256, 256>>>(dc1_offb, CIN / 16);
    k1<<<dim3(HWSZ / 64, BATCH), 256, FGEMM_SMEM>>>(x, out);

    // layer 2
    offset_partial_kernel<<<dim3(WW / 16, HH / 16, BATCH * (COUT / 16)), 128>>>(
        x, 1, dc2_offw, COUT);
    offset_reduce_kernel<<<(RED_N + 255) / 256, 256>>>(dc2_offb, COUT / 16);
    k2<<<dim3(HWSZ / 64, BATCH), 256, FGEMM_SMEM>>>(x, out);
}

// round 9
// speedup vs baseline: 1.4037x; 1.4037x over previous
#include <cuda_runtime.h>
#include <cuda_bf16.h>
#include <math.h>

#define BATCH 2
#define CIN   64
#define COUT  128
#define HH    128
#define WW    128
#define HWSZ  (HH*WW)          // 16384
#define K1    576              // 9*64
#define K2C   1152             // 9*128
#define K2    1216             // + 64 identity rows

// ---------------- scratch (static device globals) ----------------------------
__device__ float g_off[BATCH * 18 * HWSZ];
__device__ float g_offp[8 * BATCH * 18 * HWSZ];             // per-chunk partials
__device__ float g_h1 [BATCH * COUT * HWSZ];
__device__ __nv_bfloat16 g_w1h[COUT * K1], g_w1l[COUT * K1];
__device__ __nv_bfloat16 g_w2h[COUT * K2], g_w2l[COUT * K2];
__device__ float g_b1[COUT], g_b2[COUT];
__device__ float g_s1[COUT], g_s2[COUT], g_s3[COUT];

// ---------------- PTX helpers (sm_80-era only; compute_103-safe) -------------
__device__ __forceinline__ unsigned smem_u32(const void* p) {
    unsigned a;
    asm("{ .reg .u64 t; cvta.to.shared.u64 t, %1; cvt.u32.u64 %0, t; }"
        : "=r"(a) : "l"(p));
    return a;
}
__device__ __forceinline__ void cp16(unsigned dst, const void* src) {
    asm volatile("cp.async.cg.shared.global [%0], [%1], 16;"
                 :: "r"(dst), "l"(src) : "memory");
}
__device__ __forceinline__ void cp_commit() {
    asm volatile("cp.async.commit_group;" ::: "memory");
}
__device__ __forceinline__ void cp_wait0() {
    asm volatile("cp.async.wait_group 0;" ::: "memory");
}
__device__ __forceinline__ void ldm_x4(unsigned a, unsigned r[4]) {
    asm volatile("ldmatrix.sync.aligned.m8n8.x4.shared.b16 {%0,%1,%2,%3}, [%4];"
                 : "=r"(r[0]), "=r"(r[1]), "=r"(r[2]), "=r"(r[3]) : "r"(a));
}
__device__ __forceinline__ void mma16816(float d[4], const unsigned a[4],
                                         unsigned b0, unsigned b1) {
    asm volatile(
        "mma.sync.aligned.m16n8k16.row.col.f32.bf16.bf16.f32 "
        "{%0,%1,%2,%3}, {%4,%5,%6,%7}, {%8,%9}, {%0,%1,%2,%3};"
        : "+f"(d[0]), "+f"(d[1]), "+f"(d[2]), "+f"(d[3])
        : "r"(a[0]), "r"(a[1]), "r"(a[2]), "r"(a[3]), "r"(b0), "r"(b1));
}
__device__ __forceinline__ unsigned pack_bf2(float a, float b) {
    return (unsigned)__bfloat16_as_ushort(__float2bfloat16(a)) |
           ((unsigned)__bfloat16_as_ushort(__float2bfloat16(b)) << 16);
}

// ---------------- weight prep ------------------------------------------------
__global__ void prep_scales(const float* __restrict__ bn1_g, const float* __restrict__ bn1_b,
                            const float* __restrict__ bn1_m, const float* __restrict__ bn1_v,
                            const float* __restrict__ bn2_g, const float* __restrict__ bn2_b,
                            const float* __restrict__ bn2_m, const float* __restrict__ bn2_v,
                            const float* __restrict__ id_b,
                            const float* __restrict__ bn3_g, const float* __restrict__ bn3_b,
                            const float* __restrict__ bn3_m, const float* __restrict__ bn3_v)
{
    int o = threadIdx.x;
    if (o >= COUT) return;
    const float eps = 1e-5f;
    float s1 = bn1_g[o] * rsqrtf(bn1_v[o] + eps);
    float s2 = bn2_g[o] * rsqrtf(bn2_v[o] + eps);
    float s3 = bn3_g[o] * rsqrtf(bn3_v[o] + eps);
    g_s1[o] = s1; g_s2[o] = s2; g_s3[o] = s3;
    g_b1[o] = bn1_b[o] - bn1_m[o] * s1;
    g_b2[o] = (bn2_b[o] - bn2_m[o] * s2) + id_b[o] * s3 + (bn3_b[o] - bn3_m[o] * s3);
}

__device__ __forceinline__ void split_store(__nv_bfloat16* hd, __nv_bfloat16* ld,
                                            long i, float v) {
    __nv_bfloat16 h = __float2bfloat16(v);
    hd[i] = h;
    ld[i] = __float2bfloat16(v - __bfloat162float(h));
}

__global__ void prep_weights(const float* __restrict__ dc1_w,
                             const float* __restrict__ dc2_w,
                             const float* __restrict__ id_w)
{
    int idx = blockIdx.x * blockDim.x + threadIdx.x;
    const int n1 = COUT * K1, n2 = COUT * K2C, n3 = COUT * CIN;
    if (idx < n1) {
        int o = idx / K1, kk = idx % K1;
        int c = kk / 9, n = kk % 9;
        float v = dc1_w[idx] * g_s1[o];
        split_store(g_w1h, g_w1l, (long)o * K1 + n * CIN + c, v);
    } else if (idx < n1 + n2) {
        int r = idx - n1;
        int o = r / K2C, kk = r % K2C;
        int c = kk / 9, n = kk % 9;
        float v = dc2_w[r] * g_s2[o];
        split_store(g_w2h, g_w2l, (long)o * K2 + n * COUT + c, v);
    } else if (idx < n1 + n2 + n3) {
        int r = idx - n1 - n2;
        int o = r / CIN, c = r % CIN;
        float v = id_w[r] * g_s3[o];
        split_store(g_w2h, g_w2l, (long)o * K2 + K2C + c, v);
    }
}

// ---------------- offset conv: smem-tiled partial conv -----------------------
__global__ __launch_bounds__(128)
void offset_partial_kernel(const float* __restrict__ xext, int use_h1,
                           const float* __restrict__ ow, int C)
{
    __shared__ float xs[16][324];
    __shared__ float ws[16 * 9 * 18];
    const float* x = use_h1 ? g_h1 : xext;
    const int CH = C / 16;
    const int z = blockIdx.z;
    const int b = z / CH, ch = z % CH, c0 = ch * 16;
    const int tx0 = blockIdx.x * 16, ty0 = blockIdx.y * 16;
    const int t = threadIdx.x;
    const int py = t >> 4, px = t & 15;

    for (int i = t; i < 16 * 162; i += 128) {
        int c = i / 162, r = i % 162, tap = r / 18, o = r % 18;
        ws[i] = ow[o * C * 9 + (c0 + c) * 9 + tap];
    }
    for (int i = t; i < 16 * 324; i += 128) {
        int c = i / 324, rr = (i % 324) / 18, cc = i % 18;
        int gy = ty0 - 1 + rr, gx = tx0 - 1 + cc;
        float v = 0.f;
        if ((unsigned)gy < (unsigned)HH && (unsigned)gx < (unsigned)WW)
            v = x[((long)b * C + c0 + c) * HWSZ + gy * WW + gx];
        xs[c][rr * 18 + cc] = v;
    }
    __syncthreads();

    float acc[2][18];
#pragma unroll
    for (int q = 0; q < 2; ++q)
#pragma unroll
        for (int o = 0; o < 18; ++o) acc[q][o] = 0.f;

    for (int c = 0; c < 16; ++c) {
#pragma unroll
        for (int tap = 0; tap < 9; ++tap) {
            int ky = tap / 3, kx = tap % 3;
            float xv0 = xs[c][(py + ky) * 18 + px + kx];
            float xv1 = xs[c][(py + 8 + ky) * 18 + px + kx];
            const float* wrow = &ws[(c * 9 + tap) * 18];
#pragma unroll
            for (int o = 0; o < 18; ++o) {
                float w = wrow[o];
                acc[0][o] += w * xv0;
                acc[1][o] += w * xv1;
            }
        }
    }

    float* pp = g_offp + (long)ch * (BATCH * 18 * HWSZ);
#pragma unroll
    for (int q = 0; q < 2; ++q) {
        int row = ty0 + py + q * 8;
#pragma unroll
        for (int o = 0; o < 18; ++o)
            pp[((long)b * 18 + o) * HWSZ + row * WW + tx0 + px] = acc[q][o];
    }
}

__global__ void offset_reduce_kernel(const float* __restrict__ ob, int CH)
{
    int idx = blockIdx.x * blockDim.x + threadIdx.x;
    const int total = BATCH * 18 * HWSZ;
    if (idx >= total) return;
    int o = (idx / HWSZ) % 18;
    float s = ob[o];
    for (int c = 0; c < CH; ++c)
        s += g_offp[(long)c * total + idx];
    g_off[idx] = s;
}

// ---------------- fused sample + HMMA bf16x3 GEMM + bias + relu --------------
// Per CTA: 64 pixels (N) x 128 Cout (M); K-chunks of 16. B tile produced in-kernel.
// Gather mapping: warp spans 32 CONSECUTIVE pixels (pxl = tid&63) so corner
// loads coalesce; cgrp = tid>>6 covers 4 channels each.
#define ROWB2 48
#define A_MAT (128 * ROWB2)          // 6144
#define A_BUF (2 * A_MAT)            // 12288 (hi+lo)
#define B_MAT (64 * ROWB2)           // 3072
#define B_BUF (2 * B_MAT)            // 6144
#define SM_W4 0
#define SM_J4 9216
#define SM_A  18432
#define SM_B  (SM_A + 2 * A_BUF)     // 43008
#define FGEMM_SMEM (SM_B + 2 * B_BUF) // 55296

template<int C, int KTOT, int NCH, int CSH, int IDST, int SEL>
__global__ __launch_bounds__(256, 2)
void fused_gemm_kernel(const float* __restrict__ xptr, float* __restrict__ dout)
{
    extern __shared__ char sm[];
    float4* sw4 = (float4*)(sm + SM_W4);
    int4*   sj4 = (int4*)(sm + SM_J4);

    // device-side pointer resolution
    const __nv_bfloat16* Ah = SEL ? g_w2h : g_w1h;
    const __nv_bfloat16* Al = SEL ? g_w2l : g_w1l;
    const float* bias       = SEL ? g_b2  : g_b1;
    float* Cp               = SEL ? dout  : g_h1;
    const float* src        = SEL ? g_h1  : xptr;

    const int tid = threadIdx.x;
    const int warp = tid >> 5, lane = tid & 31;
    const int mbase = (warp >> 1) * 32;
    const int nbase = (warp & 1) * 32;
    const int b = blockIdx.y, j0 = blockIdx.x * 64;
    const unsigned sb = smem_u32(sm);

    // ---- precompute bilinear weights/indices for 64 px x 9 taps ----
    for (int i = tid; i < 576; i += 256) {
        int n = i >> 6, pxl = i & 63;
        int pix = j0 + pxl;
        int hh = pix >> 7, ww = pix & 127;
        float offy = g_off[(b * 18 + n)     * HWSZ + pix];
        float offx = g_off[(b * 18 + 9 + n) * HWSZ + pix];
        float py = offy + (float)(n / 3 - 1) + (float)(hh + 1);
        float px = offx + (float)(n % 3 - 1) + (float)(ww + 1);
        const float hiB = 129.f;
        py = fminf(fmaxf(py, 0.f), hiB);
        px = fminf(fmaxf(px, 0.f), hiB);
        float fy = floorf(py), fx = floorf(px);
        float qy1 = fminf(fy + 1.f, hiB), qx1 = fminf(fx + 1.f, hiB);
        float dy0 = 1.f + (fy - py), dy1 = 1.f - (qy1 - py);
        float dx0 = 1.f + (fx - px), dx1 = 1.f - (qx1 - px);
        int iy0 = (int)fy - 1, ix0 = (int)fx - 1;
        int iy1 = (int)qy1 - 1, ix1 = (int)qx1 - 1;
        bool vy0 = (unsigned)iy0 < (unsigned)HH, vy1 = (unsigned)iy1 < (unsigned)HH;
        bool vx0 = (unsigned)ix0 < (unsigned)WW, vx1 = (unsigned)ix1 < (unsigned)WW;
        float w00 = (vy0 && vx0) ? dy0 * dx0 : 0.f;
        float w01 = (vy0 && vx1) ? dy0 * dx1 : 0.f;
        float w10 = (vy1 && vx0) ? dy1 * dx0 : 0.f;
        float w11 = (vy1 && vx1) ? dy1 * dx1 : 0.f;
        int cy0 = min(max(iy0, 0), HH - 1), cy1 = min(max(iy1, 0), HH - 1);
        int cx0 = min(max(ix0, 0), WW - 1), cx1 = min(max(ix1, 0), WW - 1);
        sw4[i] = make_float4(w00, w01, w10, w11);
        sj4[i] = make_int4(cy0 * WW + cx0, cy0 * WW + cx1,
                           cy1 * WW + cx0, cy1 * WW + cx1);
    }

    float d[2][4][4];
#pragma unroll
    for (int mt = 0; mt < 2; ++mt)
#pragma unroll
        for (int nt = 0; nt < 4; ++nt)
#pragma unroll
            for (int q = 0; q < 4; ++q) d[mt][nt][q] = 0.f;

    // gather mapping: 32 consecutive pixels per warp
    const int cgrp = tid >> 6;          // 0..3, 4 channels each
    const int pxl  = tid & 63;
    const int pix  = j0 + pxl;
    const float* srcb = src + (long)b * C * HWSZ;
    const float* xb   = xptr + (long)b * CIN * HWSZ;

    float v[4];
    auto gather = [&](int ch) {
        if (ch < IDST) {
            int n = ch >> CSH, c0 = (ch & ((1 << CSH) - 1)) * 16 + cgrp * 4;
            int pi = (n << 6) | pxl;
            float4 wv = sw4[pi];
            int4 jv = sj4[pi];
#pragma unroll
            for (int u = 0; u < 4; ++u) {
                const float* pc = srcb + (long)(c0 + u) * HWSZ;
                v[u] = wv.x * pc[jv.x] + wv.y * pc[jv.y]
                     + wv.z * pc[jv.z] + wv.w * pc[jv.w];
            }
        } else {
            int c0 = (ch - IDST) * 16 + cgrp * 4;
#pragma unroll
            for (int u = 0; u < 4; ++u)
                v[u] = xb[(long)(c0 + u) * HWSZ + pix];
        }
    };
    auto storeB = [&](unsigned p) {
        unsigned h0 = pack_bf2(v[0], v[1]);
        unsigned h1 = pack_bf2(v[2], v[3]);
        unsigned l0 = pack_bf2(v[0] - __bfloat162float(__float2bfloat16(v[0])),
                               v[1] - __bfloat162float(__float2bfloat16(v[1])));
        unsigned l1 = pack_bf2(v[2] - __bfloat162float(__float2bfloat16(v[2])),
                               v[3] - __bfloat162float(__float2bfloat16(v[3])));
        char* base = sm + SM_B + p * B_BUF + pxl * ROWB2 + cgrp * 8;
        *(uint2*)(base)         = make_uint2(h0, h1);
        *(uint2*)(base + B_MAT) = make_uint2(l0, l1);
    };
    auto loadA = [&](int ch, unsigned p) {
        int k0 = ch * 16;
        int r = tid >> 1, seg = tid & 1;
        unsigned dst = sb + SM_A + p * A_BUF + r * ROWB2 + seg * 16;
        cp16(dst,         Ah + (long)r * KTOT + k0 + seg * 8);
        cp16(dst + A_MAT, Al + (long)r * KTOT + k0 + seg * 8);
        cp_commit();
    };

    const unsigned a_off = (unsigned)(mbase + (lane & 15)) * ROWB2 +
                           (unsigned)((lane >> 4) & 1) * 16u;
    const unsigned b_off = (unsigned)(nbase + (lane & 7) + (((lane >> 4) & 1) << 3)) * ROWB2 +
                           (unsigned)((lane >> 3) & 1) * 16u;

    __syncthreads();          // precomp visible
    gather(0);
    storeB(0);
    loadA(0, 0);

    unsigned p = 0;
    for (int ch = 0; ch < NCH; ++ch) {
        cp_wait0();
        __syncthreads();
        if (ch + 1 < NCH) {
            gather(ch + 1);
            loadA(ch + 1, p ^ 1);
        }
        {
            unsigned abase = sb + SM_A + p * A_BUF;
            unsigned bbase = sb + SM_B + p * B_BUF;
            unsigned ah[2][4], al[2][4], bh[2][4], bl[2][4];
#pragma unroll
            for (int mt = 0; mt < 2; ++mt) {
                unsigned addr = abase + a_off + mt * 16u * ROWB2;
                ldm_x4(addr, ah[mt]);
                ldm_x4(addr + A_MAT, al[mt]);
            }
#pragma unroll
            for (int np = 0; np < 2; ++np) {
                unsigned addr = bbase + b_off + np * 16u * ROWB2;
                ldm_x4(addr, bh[np]);
                ldm_x4(addr + B_MAT, bl[np]);
            }
#pragma unroll
            for (int mt = 0; mt < 2; ++mt) {
#pragma unroll
                for (int nt = 0; nt < 4; ++nt) {
                    int np = nt >> 1, rp = (nt & 1) * 2;
                    mma16816(d[mt][nt], ah[mt], bh[np][rp], bh[np][rp + 1]);
                    mma16816(d[mt][nt], ah[mt], bl[np][rp], bl[np][rp + 1]);
                    mma16816(d[mt][nt], al[mt], bh[np][rp], bh[np][rp + 1]);
                }
            }
        }
        if (ch + 1 < NCH) storeB(p ^ 1);
        p ^= 1;
    }

    // epilogue: bias + relu
    const int qr = lane >> 2;
    const int qc = (lane & 3) * 2;
#pragma unroll
    for (int mt = 0; mt < 2; ++mt) {
        int o0 = mbase + mt * 16 + qr;
        int o1 = o0 + 8;
        float bs0 = bias[o0], bs1 = bias[o1];
        float* row0 = Cp + ((long)b * COUT + o0) * HWSZ + j0 + nbase + qc;
        float* row1 = Cp + ((long)b * COUT + o1) * HWSZ + j0 + nbase + qc;
#pragma unroll
        for (int nt = 0; nt < 4; ++nt) {
            float* acc = d[mt][nt];
            *(float2*)(row0 + nt * 8) =
                make_float2(fmaxf(acc[0] + bs0, 0.f), fmaxf(acc[1] + bs0, 0.f));
            *(float2*)(row1 + nt * 8) =
                make_float2(fmaxf(acc[2] + bs1, 0.f), fmaxf(acc[3] + bs1, 0.f));
        }
    }
}

// ---------------- launch -----------------------------------------------------
extern "C" void kernel_launch(void* const* d_in, const int* in_sizes, int n_in,
                              void* d_out, int out_size)
{
    const float* x        = (const float*)d_in[0];
    const float* dc1_offw = (const float*)d_in[1];
    const float* dc1_offb = (const float*)d_in[2];
    const float* dc1_w    = (const float*)d_in[3];
    const float* bn1_g    = (const float*)d_in[4];
    const float* bn1_b    = (const float*)d_in[5];
    const float* bn1_m    = (const float*)d_in[6];
    const float* bn1_v    = (const float*)d_in[7];
    const float* dc2_offw = (const float*)d_in[8];
    const float* dc2_offb = (const float*)d_in[9];
    const float* dc2_w    = (const float*)d_in[10];
    const float* bn2_g    = (const float*)d_in[11];
    const float* bn2_b    = (const float*)d_in[12];
    const float* bn2_m    = (const float*)d_in[13];
    const float* bn2_v    = (const float*)d_in[14];
    const float* id_w     = (const float*)d_in[15];
    const float* id_b     = (const float*)d_in[16];
    const float* bn3_g    = (const float*)d_in[17];
    const float* bn3_b    = (const float*)d_in[18];
    const float* bn3_m    = (const float*)d_in[19];
    const float* bn3_v    = (const float*)d_in[20];
    float* out = (float*)d_out;

    // sel1: C=64, K=576, 36 chunks, 4 chunks/tap (shift 2), no identity
    auto k1 = fused_gemm_kernel<CIN, K1, 36, 2, 36, 0>;
    // sel2: C=128, K=1216, 76 chunks, 8 chunks/tap (shift 3), identity from 72
    auto k2 = fused_gemm_kernel<COUT, K2, 76, 3, 72, 1>;
    cudaFuncSetAttribute(k1, cudaFuncAttributeMaxDynamicSharedMemorySize, FGEMM_SMEM);
    cudaFuncSetAttribute(k2, cudaFuncAttributeMaxDynamicSharedMemorySize, FGEMM_SMEM);

    prep_scales<<<1, 128>>>(bn1_g, bn1_b, bn1_m, bn1_v,
                            bn2_g, bn2_b, bn2_m, bn2_v,
                            id_b, bn3_g, bn3_b, bn3_m, bn3_v);
    {
        int total = COUT * K1 + COUT * K2C + COUT * CIN;
        prep_weights<<<(total + 255) / 256, 256>>>(dc1_w, dc2_w, id_w);
    }

    const int RED_N = BATCH * 18 * HWSZ;

    // layer 1
    offset_partial_kernel<<<dim3(WW / 16, HH / 16, BATCH * (CIN / 16)), 128>>>(
        x, 0, dc1_offw, CIN);
    offset_reduce_kernel<<<(RED_N + 255) / 256, 256>>>(dc1_offb, CIN / 16);
    k1<<<dim3(HWSZ / 64, BATCH), 256, FGEMM_SMEM>>>(x, out);

    // layer 2
    offset_partial_kernel<<<dim3(WW / 16, HH / 16, BATCH * (COUT / 16)), 128>>>(
        x, 1, dc2_offw, COUT);
    offset_reduce_kernel<<<(RED_N + 255) / 256, 256>>>(dc2_offb, COUT / 16);
    k2<<<dim3(HWSZ / 64, BATCH), 256, FGEMM_SMEM>>>(x, out);
}